// round 4
// baseline (speedup 1.0000x reference)
#include <cuda_runtime.h>

// LIF recurrence: v = alpha*v + beta*c; spike = (v >= 1); v = spike ? 0 : v.
// T sequential steps (loop-carried in v), N independent neurons.
// One thread per neuron; unroll-16 over t with front-batched independent loads
// so each warp keeps ~16 cache lines (2 KB) in flight -> ~2 MB chip-wide MLP,
// enough to saturate HBM at only ~7 warps/SM.

__global__ void __launch_bounds__(128, 1)
lif_kernel(const float* __restrict__ cur,
           const float* __restrict__ v0,
           float* __restrict__ spikes,
           float* __restrict__ volts,
           int T, int N)
{
    int n = blockIdx.x * blockDim.x + threadIdx.x;
    if (n >= N) return;

    // Match reference exactly: ALPHA = float64 exp(-1/20), BETA = 1 - ALPHA
    // (both computed in double, then cast to float32 by jnp.float32).
    const float alpha = (float)0.95122942450071400910;
    const float beta  = (float)0.04877057549928599090;

    float v = v0[n];

    const size_t stride = (size_t)N;
    size_t idx = (size_t)n;

    int t = 0;
    // Main unrolled loop: batch 16 independent loads, then the dependent chain.
    for (; t + 16 <= T; t += 16) {
        float c[16];
#pragma unroll
        for (int u = 0; u < 16; ++u)
            c[u] = __ldcs(cur + idx + (size_t)u * stride);   // streaming, evict-first

#pragma unroll
        for (int u = 0; u < 16; ++u) {
            v = fmaf(alpha, v, beta * c[u]);
            const bool sp = (v >= 1.0f);
            const size_t o = idx + (size_t)u * stride;
            __stcs(spikes + o, sp ? 1.0f : 0.0f);
            v = sp ? 0.0f : v;                                // V_RESET = 0
            __stcs(volts + o, v);
        }
        idx += 16 * stride;
    }
    // Remainder (T not multiple of 16 — not hit for T=2048, kept for safety).
    for (; t < T; ++t) {
        float c = __ldcs(cur + idx);
        v = fmaf(alpha, v, beta * c);
        const bool sp = (v >= 1.0f);
        __stcs(spikes + idx, sp ? 1.0f : 0.0f);
        v = sp ? 0.0f : v;
        __stcs(volts + idx, v);
        idx += stride;
    }
}

extern "C" void kernel_launch(void* const* d_in, const int* in_sizes, int n_in,
                              void* d_out, int out_size)
{
    // metadata order: currents (T*N), v0 (N)
    const float* cur = (const float*)d_in[0];
    const float* v0  = (const float*)d_in[1];

    const int N = in_sizes[1];
    const int T = in_sizes[0] / N;

    float* out    = (float*)d_out;
    float* spikes = out;                       // first T*N elements
    float* volts  = out + (size_t)T * (size_t)N;  // second T*N elements

    const int threads = 128;
    const int blocks  = (N + threads - 1) / threads;   // 256 blocks for N=32768
    lif_kernel<<<blocks, threads>>>(cur, v0, spikes, volts, T, N);
}

// round 5
// speedup vs baseline: 1.3404x; 1.3404x over previous
#include <cuda_runtime.h>

// LIF recurrence: v = alpha*v + beta*c; spike = (v >= 1); v = spike ? 0 : v.
// T sequential steps (loop-carried in v), N independent neurons.
//
// R4: explicit double-buffered software pipeline. R3 batched loads into the
// SAME registers the compute loop consumed, so loads for block i+1 could not
// issue until block i's compute drained (WAR) -> loads in flight only ~54% of
// the time -> DRAM 52.8%. Here two 32-deep buffers ping-pong: while computing
// block i (regs A), block i+1's loads (regs B) are in flight, and vice versa.
// Continuous in-flight: 32 lines/warp x 1024 warps x 128B = 4 MB.
// Compile-time N makes every load/store offset an immediate.

// Bit-identical arithmetic to the reference:
// ALPHA = float(np.exp(-1/20)) (rounded from double), BETA = float(1 - ALPHA_double).
#define ALPHA_F ((float)0.95122942450071400910)
#define BETA_F  ((float)0.04877057549928599090)

template<int T, int N, int U>
__global__ void __launch_bounds__(32)
lif_tmpl(const float* __restrict__ cur, const float* __restrict__ v0,
         float* __restrict__ spikes, float* __restrict__ volts)
{
    const int n = blockIdx.x * blockDim.x + threadIdx.x;   // one thread per neuron
    float v = v0[n];

    const float* p  = cur    + n;
    float*       ps = spikes + n;
    float*       pv = volts  + n;

    static_assert(T % U == 0 && (T / U) % 2 == 0, "need even block count");
    constexpr int ITERS = T / U;

    float a[U], b[U];

    // Prologue: fill both buffers (blocks 0 and 1).
#pragma unroll
    for (int u = 0; u < U; ++u) a[u] = __ldcs(p + (size_t)u * N);
#pragma unroll
    for (int u = 0; u < U; ++u) b[u] = __ldcs(p + (size_t)(U + u) * N);
    p += (size_t)2 * U * N;

    // Main loop: compute A, refill A (flies during B's compute), compute B, refill B.
    for (int it = 0; it < ITERS - 2; it += 2) {
#pragma unroll
        for (int u = 0; u < U; ++u) {
            v = fmaf(ALPHA_F, v, BETA_F * a[u]);
            const bool sp = (v >= 1.0f);
            __stcs(ps + (size_t)u * N, sp ? 1.0f : 0.0f);
            v = sp ? 0.0f : v;                 // V_RESET = 0
            __stcs(pv + (size_t)u * N, v);
        }
        ps += (size_t)U * N;  pv += (size_t)U * N;
#pragma unroll
        for (int u = 0; u < U; ++u) a[u] = __ldcs(p + (size_t)u * N);
        p += (size_t)U * N;

#pragma unroll
        for (int u = 0; u < U; ++u) {
            v = fmaf(ALPHA_F, v, BETA_F * b[u]);
            const bool sp = (v >= 1.0f);
            __stcs(ps + (size_t)u * N, sp ? 1.0f : 0.0f);
            v = sp ? 0.0f : v;
            __stcs(pv + (size_t)u * N, v);
        }
        ps += (size_t)U * N;  pv += (size_t)U * N;
#pragma unroll
        for (int u = 0; u < U; ++u) b[u] = __ldcs(p + (size_t)u * N);
        p += (size_t)U * N;
    }

    // Epilogue: last two blocks, no refills.
#pragma unroll
    for (int u = 0; u < U; ++u) {
        v = fmaf(ALPHA_F, v, BETA_F * a[u]);
        const bool sp = (v >= 1.0f);
        __stcs(ps + (size_t)u * N, sp ? 1.0f : 0.0f);
        v = sp ? 0.0f : v;
        __stcs(pv + (size_t)u * N, v);
    }
    ps += (size_t)U * N;  pv += (size_t)U * N;
#pragma unroll
    for (int u = 0; u < U; ++u) {
        v = fmaf(ALPHA_F, v, BETA_F * b[u]);
        const bool sp = (v >= 1.0f);
        __stcs(ps + (size_t)u * N, sp ? 1.0f : 0.0f);
        v = sp ? 0.0f : v;
        __stcs(pv + (size_t)u * N, v);
    }
}

// Generic fallback (any T, N) — R3's correct kernel, unspecialized shapes only.
__global__ void lif_generic(const float* __restrict__ cur, const float* __restrict__ v0,
                            float* __restrict__ spikes, float* __restrict__ volts,
                            int T, int N)
{
    int n = blockIdx.x * blockDim.x + threadIdx.x;
    if (n >= N) return;
    float v = v0[n];
    size_t idx = (size_t)n;
    for (int t = 0; t < T; ++t) {
        float c = __ldcs(cur + idx);
        v = fmaf(ALPHA_F, v, BETA_F * c);
        const bool sp = (v >= 1.0f);
        __stcs(spikes + idx, sp ? 1.0f : 0.0f);
        v = sp ? 0.0f : v;
        __stcs(volts + idx, v);
        idx += (size_t)N;
    }
}

extern "C" void kernel_launch(void* const* d_in, const int* in_sizes, int n_in,
                              void* d_out, int out_size)
{
    // metadata order: currents (T*N), v0 (N)
    const float* cur = (const float*)d_in[0];
    const float* v0  = (const float*)d_in[1];

    const int N = in_sizes[1];
    const int T = in_sizes[0] / N;

    float* out    = (float*)d_out;
    float* spikes = out;                          // first T*N elements
    float* volts  = out + (size_t)T * (size_t)N;  // second T*N elements

    if (T == 2048 && N == 32768) {
        // 32-thread blocks: 1024 blocks over 148 SMs -> 7 vs 6 per SM (1.2% imbalance).
        lif_tmpl<2048, 32768, 32><<<1024, 32>>>(cur, v0, spikes, volts);
    } else {
        const int threads = 128;
        lif_generic<<<(N + threads - 1) / threads, threads>>>(cur, v0, spikes, volts, T, N);
    }
}